// round 8
// baseline (speedup 1.0000x reference)
#include <cuda_runtime.h>

#define S 2048
#define B 32
#define H 1024

// ---- proj config: 1024 blocks for latency tolerance ----
#define K1_TH 128
#define K1_KC 16            // k per block (64 splits)
#define K1_BT 16            // b per block (2 tiles)

// ---- energy config (R2-proven shape, untouched inner loop) ----
#define K2_WARPS 8
#define K2_ROWS (K2_WARPS * 2)      // 16 s-rows per block
#define NGRP    (S / K2_ROWS)       // 128 blocks per b

// Scratch (zero-init at load; each replay restores its own zeros).
__device__ float g_v[B * H];        // v[b,h] = sum_k dec[b,k] * W[k,h]
__device__ float g_energy[B * S];   // energies[b,s]
__device__ int   g_cnt[B];          // completion tickets per b

// ---------------------------------------------------------------------------
// v[b,h] += sum_{k in chunk} dec[b,k] * W[k,h]
// grid: (H/K1_TH, H/K1_KC, B/K1_BT) = (8, 64, 2) = 1024 blocks.
__global__ __launch_bounds__(K1_TH) void proj_kernel(
    const float* __restrict__ dec,   // [B, H]
    const float* __restrict__ W)     // [H, H], W[k*H + h]
{
    __shared__ float s_dec[K1_BT][K1_KC];
    const int h  = blockIdx.x * K1_TH + threadIdx.x;
    const int k0 = blockIdx.y * K1_KC;
    const int b0 = blockIdx.z * K1_BT;

    // FIX(R7): K1_BT*K1_KC = 256 > 128 threads -> must stride, not predicate.
    for (int i = threadIdx.x; i < K1_BT * K1_KC; i += K1_TH) {
        int b = i / K1_KC, k = i % K1_KC;
        s_dec[b][k] = dec[(b0 + b) * H + k0 + k];
    }
    __syncthreads();

    float acc[K1_BT];
#pragma unroll
    for (int b = 0; b < K1_BT; b++) acc[b] = 0.0f;

#pragma unroll
    for (int kk = 0; kk < K1_KC; kk += 8) {
        float w[8];
#pragma unroll
        for (int u = 0; u < 8; u++)
            w[u] = __ldg(&W[(size_t)(k0 + kk + u) * H + h]);
#pragma unroll
        for (int u = 0; u < 8; u++) {
#pragma unroll
            for (int b = 0; b < K1_BT; b++)
                acc[b] = fmaf(s_dec[b][kk + u], w[u], acc[b]);
        }
    }

#pragma unroll
    for (int b = 0; b < K1_BT; b++)
        atomicAdd(&g_v[(b0 + b) * H + h], acc[b]);
}

// ---------------------------------------------------------------------------
// energies[b,s] = v[b] . enc[s,b,:]  (streams 256 MB) + fused tail softmax:
// the last-finishing block of each b normalizes that row and resets state.
// grid: (S/K2_ROWS, B) = (128, 32) = 4096 blocks of 256 threads.
__global__ __launch_bounds__(32 * K2_WARPS) void energy_kernel(
    const float* __restrict__ enc,   // [S, B, H]
    float* __restrict__ out)         // [B, S]
{
    __shared__ float4 s_v[H / 4];
    __shared__ float  s_red[K2_WARPS];
    __shared__ int    s_last;
    const int b = blockIdx.y;

    const float4* vb = reinterpret_cast<const float4*>(&g_v[b * H]);
    for (int i = threadIdx.x; i < H / 4; i += blockDim.x) s_v[i] = vb[i];
    __syncthreads();

    const int warp = threadIdx.x >> 5;
    const int lane = threadIdx.x & 31;
    const int s0 = blockIdx.x * K2_ROWS + warp;          // row 1
    const int s1 = s0 + K2_WARPS;                        // row 2

    const float4* e0 =
        reinterpret_cast<const float4*>(&enc[((size_t)s0 * B + b) * (size_t)H]);
    const float4* e1 =
        reinterpret_cast<const float4*>(&enc[((size_t)s1 * B + b) * (size_t)H]);

    float acc0 = 0.0f, acc1 = 0.0f;
#pragma unroll
    for (int j = 0; j < (H / 4) / 32; j++) {   // 8 float4 iterations per row
        float4 a = __ldcs(&e0[lane + j * 32]); // streaming: don't pollute L2
        float4 c = __ldcs(&e1[lane + j * 32]);
        float4 vv = s_v[lane + j * 32];
        acc0 = fmaf(a.x, vv.x, acc0);
        acc0 = fmaf(a.y, vv.y, acc0);
        acc0 = fmaf(a.z, vv.z, acc0);
        acc0 = fmaf(a.w, vv.w, acc0);
        acc1 = fmaf(c.x, vv.x, acc1);
        acc1 = fmaf(c.y, vv.y, acc1);
        acc1 = fmaf(c.z, vv.z, acc1);
        acc1 = fmaf(c.w, vv.w, acc1);
    }

#pragma unroll
    for (int o = 16; o > 0; o >>= 1) {
        acc0 += __shfl_down_sync(0xffffffffu, acc0, o);
        acc1 += __shfl_down_sync(0xffffffffu, acc1, o);
    }

    if (lane == 0) {
        g_energy[b * S + s0] = acc0;
        g_energy[b * S + s1] = acc1;
    }

    // ---- completion ticket: last block of this b runs the softmax ----
    __threadfence();          // make my energy stores visible device-wide
    __syncthreads();          // all warps' stores+fences done
    if (threadIdx.x == 0)
        s_last = (atomicAdd(&g_cnt[b], 1) == NGRP - 1);
    __syncthreads();
    if (!s_last) return;

    __threadfence();          // acquire: see all other blocks' energies
    const float* e = &g_energy[b * S];
    const int tid = threadIdx.x;

    float vals[S / 256];      // 8 per thread
    float m = -1e30f;
#pragma unroll
    for (int j = 0; j < S / 256; j++) {
        vals[j] = e[tid + j * 256];
        m = fmaxf(m, vals[j]);
    }
#pragma unroll
    for (int o = 16; o > 0; o >>= 1)
        m = fmaxf(m, __shfl_xor_sync(0xffffffffu, m, o));
    if (lane == 0) s_red[warp] = m;
    __syncthreads();
#pragma unroll
    for (int w = 0; w < K2_WARPS; w++) m = fmaxf(m, s_red[w]);
    __syncthreads();

    float sum = 0.0f;
#pragma unroll
    for (int j = 0; j < S / 256; j++) {
        vals[j] = __expf(vals[j] - m);
        sum += vals[j];
    }
#pragma unroll
    for (int o = 16; o > 0; o >>= 1)
        sum += __shfl_xor_sync(0xffffffffu, sum, o);
    if (lane == 0) s_red[warp] = sum;
    __syncthreads();
    float total = 0.0f;
#pragma unroll
    for (int w = 0; w < K2_WARPS; w++) total += s_red[w];

    const float inv = __frcp_rn(total);
#pragma unroll
    for (int j = 0; j < S / 256; j++)
        out[b * S + tid + j * 256] = vals[j] * inv;

    // Reset state for the next graph replay. All readers of g_v[b] (the 128
    // blocks of this b) have already passed their reads (they incremented the
    // ticket afterwards), so zeroing is race-free.
    for (int i = tid; i < H; i += 256) g_v[b * H + i] = 0.0f;
    if (tid == 0) g_cnt[b] = 0;
}

// ---------------------------------------------------------------------------
extern "C" void kernel_launch(void* const* d_in, const int* in_sizes, int n_in,
                              void* d_out, int out_size)
{
    const float* dec = (const float*)d_in[0];   // rnn_outputs [1,B,H]
    const float* enc = (const float*)d_in[1];   // encoder_outputs [S,B,H]
    const float* W   = (const float*)d_in[2];   // W_attn [H,H]
    // d_in[3] = b_attn: constant over s per batch -> cancelled by softmax.
    float* out = (float*)d_out;                 // [B,S] float32

    proj_kernel<<<dim3(H / K1_TH, H / K1_KC, B / K1_BT), K1_TH>>>(dec, W);
    energy_kernel<<<dim3(S / K2_ROWS, B), 32 * K2_WARPS>>>(enc, out);
}

// round 9
// speedup vs baseline: 1.0545x; 1.0545x over previous
#include <cuda_runtime.h>

#define S 2048
#define B 32
#define H 1024

// ---- proj config: 1024 blocks for latency tolerance (R8-proven) ----
#define K1_TH 128
#define K1_KC 16            // k per block (64 splits)
#define K1_BT 16            // b per block (2 tiles)

// ---- energy config (R2/R6-proven shape) ----
#define K2_WARPS 8
#define K2_ROWS (K2_WARPS * 2)      // 16 s-rows per block

// Scratch (zero-init at load; softmax re-zeroes g_v each replay).
__device__ float g_v[B * H];        // v[b,h] = sum_k dec[b,k] * W[k,h]
__device__ float g_energy[B * S];   // energies[b,s]

// ---------------------------------------------------------------------------
// v[b,h] += sum_{k in chunk} dec[b,k] * W[k,h]
// grid: (H/K1_TH, H/K1_KC, B/K1_BT) = (8, 64, 2) = 1024 blocks.
__global__ __launch_bounds__(K1_TH) void proj_kernel(
    const float* __restrict__ dec,   // [B, H]
    const float* __restrict__ W)     // [H, H], W[k*H + h]
{
    __shared__ float s_dec[K1_BT][K1_KC];
    const int h  = blockIdx.x * K1_TH + threadIdx.x;
    const int k0 = blockIdx.y * K1_KC;
    const int b0 = blockIdx.z * K1_BT;

    for (int i = threadIdx.x; i < K1_BT * K1_KC; i += K1_TH) {
        int b = i / K1_KC, k = i % K1_KC;
        s_dec[b][k] = dec[(b0 + b) * H + k0 + k];
    }
    __syncthreads();

    float acc[K1_BT];
#pragma unroll
    for (int b = 0; b < K1_BT; b++) acc[b] = 0.0f;

#pragma unroll
    for (int kk = 0; kk < K1_KC; kk += 8) {
        float w[8];
#pragma unroll
        for (int u = 0; u < 8; u++)
            w[u] = __ldg(&W[(size_t)(k0 + kk + u) * H + h]);
#pragma unroll
        for (int u = 0; u < 8; u++) {
#pragma unroll
            for (int b = 0; b < K1_BT; b++)
                acc[b] = fmaf(s_dec[b][kk + u], w[u], acc[b]);
        }
    }

#pragma unroll
    for (int b = 0; b < K1_BT; b++)
        atomicAdd(&g_v[(b0 + b) * H + h], acc[b]);
}

// ---------------------------------------------------------------------------
// energies[b,s] = v[b] . enc[s,b,:]   (dominant, streams 256 MB). Clean R6
// version: no fences, no tickets, stores only energies.
// grid: (S/K2_ROWS, B) = (128, 32) = 4096 blocks of 256 threads.
__global__ __launch_bounds__(32 * K2_WARPS) void energy_kernel(
    const float* __restrict__ enc)   // [S, B, H]
{
    __shared__ float4 s_v[H / 4];
    const int b = blockIdx.y;

    const float4* vb = reinterpret_cast<const float4*>(&g_v[b * H]);
    for (int i = threadIdx.x; i < H / 4; i += blockDim.x) s_v[i] = vb[i];
    __syncthreads();

    const int warp = threadIdx.x >> 5;
    const int lane = threadIdx.x & 31;
    const int s0 = blockIdx.x * K2_ROWS + warp;          // row 1
    const int s1 = s0 + K2_WARPS;                        // row 2

    const float4* e0 =
        reinterpret_cast<const float4*>(&enc[((size_t)s0 * B + b) * (size_t)H]);
    const float4* e1 =
        reinterpret_cast<const float4*>(&enc[((size_t)s1 * B + b) * (size_t)H]);

    float acc0 = 0.0f, acc1 = 0.0f;
#pragma unroll
    for (int j = 0; j < (H / 4) / 32; j++) {   // 8 float4 iterations per row
        float4 a = __ldcs(&e0[lane + j * 32]); // streaming: don't pollute L2
        float4 c = __ldcs(&e1[lane + j * 32]);
        float4 vv = s_v[lane + j * 32];
        acc0 = fmaf(a.x, vv.x, acc0);
        acc0 = fmaf(a.y, vv.y, acc0);
        acc0 = fmaf(a.z, vv.z, acc0);
        acc0 = fmaf(a.w, vv.w, acc0);
        acc1 = fmaf(c.x, vv.x, acc1);
        acc1 = fmaf(c.y, vv.y, acc1);
        acc1 = fmaf(c.z, vv.z, acc1);
        acc1 = fmaf(c.w, vv.w, acc1);
    }

#pragma unroll
    for (int o = 16; o > 0; o >>= 1) {
        acc0 += __shfl_down_sync(0xffffffffu, acc0, o);
        acc1 += __shfl_down_sync(0xffffffffu, acc1, o);
    }

    if (lane == 0) {
        g_energy[b * S + s0] = acc0;
        g_energy[b * S + s1] = acc1;
    }
}

// ---------------------------------------------------------------------------
// softmax over s for each b; also re-zeroes g_v[b] for the next replay.
// grid: B blocks of 1024 threads, 2 elems/thread.
#define K3_TH 1024
__global__ __launch_bounds__(K3_TH) void softmax_kernel(float* __restrict__ out)
{
    __shared__ float red[K3_TH / 32];
    const int b = blockIdx.x;
    const int tid = threadIdx.x;
    const int lane = tid & 31, warp = tid >> 5;
    const float* e = &g_energy[b * S];

    // Re-zero g_v[b,:] (already consumed by energy_kernel this replay).
    g_v[b * H + tid] = 0.0f;

    float vals[S / K3_TH];
    float m = -1e30f;
#pragma unroll
    for (int j = 0; j < S / K3_TH; j++) {
        vals[j] = e[tid + j * K3_TH];
        m = fmaxf(m, vals[j]);
    }
#pragma unroll
    for (int o = 16; o > 0; o >>= 1)
        m = fmaxf(m, __shfl_xor_sync(0xffffffffu, m, o));
    if (lane == 0) red[warp] = m;
    __syncthreads();
#pragma unroll
    for (int w = 0; w < K3_TH / 32; w++) m = fmaxf(m, red[w]);
    __syncthreads();

    float sum = 0.0f;
#pragma unroll
    for (int j = 0; j < S / K3_TH; j++) {
        vals[j] = __expf(vals[j] - m);
        sum += vals[j];
    }
#pragma unroll
    for (int o = 16; o > 0; o >>= 1)
        sum += __shfl_xor_sync(0xffffffffu, sum, o);
    if (lane == 0) red[warp] = sum;
    __syncthreads();
    float total = 0.0f;
#pragma unroll
    for (int w = 0; w < K3_TH / 32; w++) total += red[w];

    const float inv = __frcp_rn(total);
#pragma unroll
    for (int j = 0; j < S / K3_TH; j++)
        out[b * S + tid + j * K3_TH] = vals[j] * inv;
}

// ---------------------------------------------------------------------------
extern "C" void kernel_launch(void* const* d_in, const int* in_sizes, int n_in,
                              void* d_out, int out_size)
{
    const float* dec = (const float*)d_in[0];   // rnn_outputs [1,B,H]
    const float* enc = (const float*)d_in[1];   // encoder_outputs [S,B,H]
    const float* W   = (const float*)d_in[2];   // W_attn [H,H]
    // d_in[3] = b_attn: constant over s per batch -> cancelled by softmax.
    float* out = (float*)d_out;                 // [B,S] float32

    proj_kernel<<<dim3(H / K1_TH, H / K1_KC, B / K1_BT), K1_TH>>>(dec, W);
    energy_kernel<<<dim3(S / K2_ROWS, B), 32 * K2_WARPS>>>(enc);
    softmax_kernel<<<B, K3_TH>>>(out);
}